// round 1
// baseline (speedup 1.0000x reference)
#include <cuda_runtime.h>
#include <math.h>

#define N_NODES   8192
#define HIDDEN    256
#define HEADS     4
#define HEAD_DIM  64
#define NUM_EDGES 4096
#define NUM_INC   65536
#define OUT_ELEMS (N_NODES*HIDDEN)

// ---------------- scratch (device globals; no allocation allowed) ----------------
__device__ float    g_v[HEADS*HIDDEN];
__device__ float    g_bh[HEADS];
__device__ float    g_nlogit[N_NODES*HEADS];
__device__ unsigned g_segmax[NUM_EDGES*HEADS];
__device__ float    g_segsum[NUM_EDGES*HEADS];
__device__ int      g_ecount[NUM_EDGES];
__device__ int      g_estart[NUM_EDGES+1];
__device__ int      g_efill[NUM_EDGES];
__device__ int      g_perm[NUM_INC];
__device__ float    g_attn[NUM_INC];
__device__ float    g_nattn[N_NODES];
__device__ int      g_ncount[N_NODES];

// monotone float<->uint mapping for atomicMax on floats
__device__ __forceinline__ unsigned f2u(float f){
    unsigned u = __float_as_uint(f);
    return (u & 0x80000000u) ? ~u : (u | 0x80000000u);
}
__device__ __forceinline__ float u2f(unsigned u){
    return __uint_as_float((u & 0x80000000u) ? (u & 0x7fffffffu) : ~u);
}

// ---------------- init small scratch ----------------
__global__ void k_init(){
    int i = blockIdx.x*blockDim.x + threadIdx.x;
    if (i < NUM_EDGES*HEADS){ g_segmax[i] = 0u; g_segsum[i] = 0.f; }
    if (i < NUM_EDGES)      { g_ecount[i] = 0; g_efill[i] = 0; }
    if (i < N_NODES)        { g_nattn[i] = 0.f; g_ncount[i] = 0; }
}

// ---------------- zero the attention_weights region ----------------
__global__ void k_zero(float4* __restrict__ p, long n4){
    long i = (long)blockIdx.x*blockDim.x + threadIdx.x;
    long stride = (long)gridDim.x*blockDim.x;
    float4 z = make_float4(0.f,0.f,0.f,0.f);
    for (; i < n4; i += stride) p[i] = z;
}

// ---------------- v_h = edge_att_h^T W_w_h  (folds first GEMM away) ----------------
__global__ void k_prep(const float* __restrict__ W_w, const float* __restrict__ W_b,
                       const float* __restrict__ att){
    int k = threadIdx.x;  // 256 threads
    #pragma unroll
    for (int h = 0; h < HEADS; h++){
        float s = 0.f;
        #pragma unroll 8
        for (int d = 0; d < HEAD_DIM; d++)
            s += W_w[(h*HEAD_DIM + d)*HIDDEN + k] * att[h*HEAD_DIM + d];
        g_v[h*HIDDEN + k] = s;
    }
    if (k < HEADS){
        float s = 0.f;
        #pragma unroll 8
        for (int d = 0; d < HEAD_DIM; d++)
            s += W_b[k*HEAD_DIM + d] * att[k*HEAD_DIM + d];
        g_bh[k] = s;
    }
}

// ---------------- node_logits[n,h] = x[n]·v_h + b_h  (warp per node) ----------------
__global__ void k_nlogit(const float* __restrict__ x){
    __shared__ float sv[HEADS*HIDDEN];
    for (int i = threadIdx.x; i < HEADS*HIDDEN; i += blockDim.x) sv[i] = g_v[i];
    __syncthreads();
    int warp = threadIdx.x >> 5, lane = threadIdx.x & 31;
    int n = blockIdx.x*8 + warp;
    const float* xr = x + (long)n*HIDDEN;
    float acc[HEADS] = {0.f,0.f,0.f,0.f};
    #pragma unroll
    for (int j = 0; j < 8; j++){
        float xv = xr[lane + 32*j];
        #pragma unroll
        for (int h = 0; h < HEADS; h++) acc[h] += xv * sv[h*HIDDEN + lane + 32*j];
    }
    #pragma unroll
    for (int h = 0; h < HEADS; h++)
        #pragma unroll
        for (int off = 16; off; off >>= 1)
            acc[h] += __shfl_xor_sync(0xffffffffu, acc[h], off);
    if (lane < HEADS) g_nlogit[n*HEADS + lane] = acc[lane] + g_bh[lane];
}

// ---------------- pass 1: per-edge counts + segment max, per-node counts ----------------
__global__ void k_inc1(const int* __restrict__ node_idx, const int* __restrict__ edge_idx){
    int i = blockIdx.x*blockDim.x + threadIdx.x;
    if (i >= NUM_INC) return;
    int e = edge_idx[i], n = node_idx[i];
    atomicAdd(&g_ecount[e], 1);
    atomicAdd(&g_ncount[n], 1);
    #pragma unroll
    for (int h = 0; h < HEADS; h++)
        atomicMax(&g_segmax[e*HEADS + h], f2u(g_nlogit[n*HEADS + h]));
}

// ---------------- exclusive prefix sum over 4096 edge counts (1 block) ----------------
__global__ void k_scan(){
    __shared__ int sh[1024];
    int t = threadIdx.x;
    int c0 = g_ecount[t*4+0], c1 = g_ecount[t*4+1];
    int c2 = g_ecount[t*4+2], c3 = g_ecount[t*4+3];
    int s0 = c0, s1 = s0+c1, s2 = s1+c2, s3 = s2+c3;
    sh[t] = s3;
    __syncthreads();
    for (int off = 1; off < 1024; off <<= 1){
        int v = (t >= off) ? sh[t-off] : 0;
        __syncthreads();
        sh[t] += v;
        __syncthreads();
    }
    int prev = t ? sh[t-1] : 0;
    g_estart[t*4+0] = prev;
    g_estart[t*4+1] = prev + s0;
    g_estart[t*4+2] = prev + s1;
    g_estart[t*4+3] = prev + s2;
    if (t == 1023) g_estart[4096] = sh[1023];
}

// ---------------- pass 2: exp-sum per (edge,head) + CSR fill ----------------
__global__ void k_inc2(const int* __restrict__ node_idx, const int* __restrict__ edge_idx){
    int i = blockIdx.x*blockDim.x + threadIdx.x;
    if (i >= NUM_INC) return;
    int e = edge_idx[i], n = node_idx[i];
    #pragma unroll
    for (int h = 0; h < HEADS; h++){
        float p = expf(g_nlogit[n*HEADS + h] - u2f(g_segmax[e*HEADS + h]));
        atomicAdd(&g_segsum[e*HEADS + h], p);
    }
    int pos = atomicAdd(&g_efill[e], 1);
    g_perm[g_estart[e] + pos] = i;
}

// ---------------- pass 3: attn_mean per incidence + per-node attn sum ----------------
__global__ void k_inc3(const int* __restrict__ node_idx, const int* __restrict__ edge_idx){
    int i = blockIdx.x*blockDim.x + threadIdx.x;
    if (i >= NUM_INC) return;
    int e = edge_idx[i], n = node_idx[i];
    float a = 0.f;
    if (g_ecount[e] >= 2){
        #pragma unroll
        for (int h = 0; h < HEADS; h++){
            float p = expf(g_nlogit[n*HEADS + h] - u2f(g_segmax[e*HEADS + h]));
            a += p / g_segsum[e*HEADS + h];
        }
        a *= 0.25f;
    }
    g_attn[i] = a;
    atomicAdd(&g_nattn[n], a);
}

// ---------------- sparse A@B^T: per-edge pairwise scatter (warp per edge) ----------------
__global__ void k_scatter(const int* __restrict__ node_idx, float* __restrict__ AW){
    int warp = (blockIdx.x*blockDim.x + threadIdx.x) >> 5;
    int lane = threadIdx.x & 31;
    if (warp >= NUM_EDGES) return;
    int s = g_estart[warp];
    int k = g_ecount[warp];
    int total = k*k;
    for (int t = lane; t < total; t += 32){
        int a = t / k, b = t - a*k;
        int ia = g_perm[s+a], ib = g_perm[s+b];
        int na = node_idx[ia], nb = node_idx[ib];
        if (na != nb){
            float v = g_attn[ia];
            if (v != 0.f) atomicAdd(&AW[(long)na*N_NODES + nb], v);
        }
    }
}

// ---------------- y = (x*scale) @ out_w^T + out_b, then LayerNorm, fused ----------------
// 64 rows x 256 cols per block; 256 threads; thread micro-tile = 4 rows x 16 cols
// (cols strided by 16 for conflict-free smem reads)
#define MT 64
#define KT 32
__global__ __launch_bounds__(256) void k_gemm_ln(const float* __restrict__ x,
                                                 const float* __restrict__ out_w,
                                                 const float* __restrict__ out_b,
                                                 float* __restrict__ out){
    __shared__ float As[KT][MT+1];       // [k][m]
    __shared__ float Bs[KT][HIDDEN+1];   // [k][j]
    __shared__ float Ss[MT];
    int tid = threadIdx.x;
    int tx = tid & 15;      // col group (col = tx + 16*j)
    int ty = tid >> 4;      // row group (row = row0 + ty*4 + i)
    int row0 = blockIdx.x * MT;

    if (tid < MT){
        int rr = row0 + tid;
        float c = (float)g_ncount[rr];
        Ss[tid] = g_nattn[rr] / fmaxf(c, 1.0f);
    }
    __syncthreads();

    float acc[4][16];
    #pragma unroll
    for (int i = 0; i < 4; i++)
        #pragma unroll
        for (int j = 0; j < 16; j++) acc[i][j] = 0.f;

    for (int k0 = 0; k0 < HIDDEN; k0 += KT){
        #pragma unroll
        for (int r = 0; r < 8; r++){           // A: 64x32 = 2048 elems
            int q = tid + 256*r;
            int m = q >> 5, k = q & 31;
            As[k][m] = x[(long)(row0+m)*HIDDEN + k0 + k] * Ss[m];
        }
        #pragma unroll
        for (int r = 0; r < 32; r++){          // B: 256x32 = 8192 elems
            int q = tid + 256*r;
            int j = q >> 5, k = q & 31;
            Bs[k][j] = out_w[(long)j*HIDDEN + k0 + k];
        }
        __syncthreads();
        #pragma unroll
        for (int k = 0; k < KT; k++){
            float a[4], b[16];
            #pragma unroll
            for (int i = 0; i < 4; i++) a[i] = As[k][ty*4 + i];
            #pragma unroll
            for (int j = 0; j < 16; j++) b[j] = Bs[k][tx + 16*j];
            #pragma unroll
            for (int i = 0; i < 4; i++)
                #pragma unroll
                for (int j = 0; j < 16; j++) acc[i][j] += a[i]*b[j];
        }
        __syncthreads();
    }

    // bias
    #pragma unroll
    for (int j = 0; j < 16; j++){
        float bb = out_b[tx + 16*j];
        #pragma unroll
        for (int i = 0; i < 4; i++) acc[i][j] += bb;
    }

    // LayerNorm per row: reduce across the 16 tx threads (contiguous half-warp group)
    #pragma unroll
    for (int i = 0; i < 4; i++){
        float s = 0.f, s2 = 0.f;
        #pragma unroll
        for (int j = 0; j < 16; j++){ s += acc[i][j]; s2 += acc[i][j]*acc[i][j]; }
        #pragma unroll
        for (int off = 8; off; off >>= 1){
            s  += __shfl_xor_sync(0xffffffffu, s,  off);
            s2 += __shfl_xor_sync(0xffffffffu, s2, off);
        }
        float mu  = s * (1.f/256.f);
        float var = s2 * (1.f/256.f) - mu*mu;
        float inv = rsqrtf(var + 1e-5f);
        int row = row0 + ty*4 + i;
        float* op = out + (long)row*HIDDEN;
        #pragma unroll
        for (int j = 0; j < 16; j++)
            op[tx + 16*j] = (acc[i][j] - mu) * inv;
    }
}

// ---------------- launch ----------------
extern "C" void kernel_launch(void* const* d_in, const int* in_sizes, int n_in,
                              void* d_out, int out_size){
    const float* x        = (const float*)d_in[0];
    const int*   node_idx = (const int*)  d_in[1];
    const int*   edge_idx = (const int*)  d_in[2];
    const float* W_w      = (const float*)d_in[3];
    const float* W_b      = (const float*)d_in[4];
    const float* att      = (const float*)d_in[5];
    const float* out_w    = (const float*)d_in[6];
    const float* out_b    = (const float*)d_in[7];
    float* out = (float*)d_out;
    float* AW  = out + OUT_ELEMS;
    long aw_elems = (long)N_NODES * N_NODES;

    k_init<<<64, 256>>>();
    k_zero<<<4096, 256>>>((float4*)AW, aw_elems/4);
    k_prep<<<1, 256>>>(W_w, W_b, att);
    k_nlogit<<<N_NODES/8, 256>>>(x);
    k_inc1<<<NUM_INC/256, 256>>>(node_idx, edge_idx);
    k_scan<<<1, 1024>>>();
    k_inc2<<<NUM_INC/256, 256>>>(node_idx, edge_idx);
    k_inc3<<<NUM_INC/256, 256>>>(node_idx, edge_idx);
    k_scatter<<<NUM_EDGES/8, 256>>>(node_idx, AW);
    k_gemm_ln<<<N_NODES/MT, 256>>>(x, out_w, out_b, out);
}